// round 12
// baseline (speedup 1.0000x reference)
#include <cuda_runtime.h>
#include <cuda_bf16.h>
#include <stdint.h>
#include <math.h>

// ---------------- problem constants ----------------
#define BATCH   8
#define SEQ     4096
#define DM      1024
#define NS      256
#define M_ROWS  (BATCH*SEQ)     // 32768
#define CHUNK   128
#define NCHUNK  (SEQ/CHUNK)     // 32

// ---------------- scratch ----------------
__device__ float g_a[M_ROWS * NS];
__device__ float g_b[M_ROWS * NS];
__device__ float g_pref[BATCH * NCHUNK * NS];   // inclusive prefix per chunk
__device__ int   g_flag[BATCH * NCHUNK];

__device__ __nv_bfloat16 g_xhi[M_ROWS * DM], g_xlo[M_ROWS * DM];
__device__ __nv_bfloat16 g_hhi[M_ROWS * NS], g_hlo[M_ROWS * NS];
__device__ __nv_bfloat16 g_wahi[NS * DM],  g_walo[NS * DM];
__device__ __nv_bfloat16 g_bwhi[NS * DM],  g_bwlo[NS * DM];
__device__ __nv_bfloat16 g_chi[DM * NS],   g_clo[DM * NS];
__device__ __nv_bfloat16 g_dhi[DM * DM],   g_dlo[DM * DM];

// ---------------- GEMM config (128x128, 2 CTA/SM) ----------------
#define LDS_EL  40
#define A_SZ    (128 * LDS_EL * 2)      // 10240 B
#define STAGE   (4 * A_SZ)              // 40960 B
#define SMEM_TOTAL (2 * STAGE)          // 81920 B

// ---------------- PTX helpers ----------------
__device__ __forceinline__ uint32_t smem_u32(const void* p) {
    uint32_t a;
    asm("{ .reg .u64 t; cvta.to.shared.u64 t, %1; cvt.u32.u64 %0, t; }" : "=r"(a) : "l"(p));
    return a;
}
__device__ __forceinline__ void cp16(uint32_t d, const void* s) {
    asm volatile("cp.async.cg.shared.global [%0], [%1], 16;" :: "r"(d), "l"(s));
}
#define CP_COMMIT() asm volatile("cp.async.commit_group;" ::: "memory")
#define CP_WAIT(N)  asm volatile("cp.async.wait_group %0;" :: "n"(N) : "memory")

__device__ __forceinline__ void ldm4(uint32_t* r, uint32_t a) {
    asm volatile("ldmatrix.sync.aligned.m8n8.x4.shared.b16 {%0,%1,%2,%3}, [%4];"
        : "=r"(r[0]), "=r"(r[1]), "=r"(r[2]), "=r"(r[3]) : "r"(a));
}
__device__ __forceinline__ void mma16(float* c, const uint32_t* a, const uint32_t* b) {
    asm volatile("mma.sync.aligned.m16n8k16.row.col.f32.bf16.bf16.f32 "
        "{%0,%1,%2,%3}, {%4,%5,%6,%7}, {%8,%9}, {%0,%1,%2,%3};"
        : "+f"(c[0]), "+f"(c[1]), "+f"(c[2]), "+f"(c[3])
        : "r"(a[0]), "r"(a[1]), "r"(a[2]), "r"(a[3]), "r"(b[0]), "r"(b[1]));
}

// ---------------- per-slab compute: 3-pass bf16 compensation ----------------
__device__ __forceinline__ void compute_slab(uint32_t stg, float acc[4][4][4],
                                             int wr, int wc, int lane)
{
    const uint32_t aoff = ((wr * 64 + (lane & 15)) * LDS_EL + (lane >> 4) * 8) * 2;
    const uint32_t boff = ((wc * 32 + (lane & 15)) * LDS_EL + (lane >> 4) * 8) * 2;
    #pragma unroll
    for (int ks = 0; ks < 2; ks++) {
        const uint32_t kb = ks * 32;   // 16 bf16 = 32 B
        uint32_t ahi[4][4];
        #pragma unroll
        for (int i = 0; i < 4; i++) ldm4(ahi[i], stg + aoff + kb + i * (16 * LDS_EL * 2));

        uint32_t bh[4][2];
        {
            uint32_t t0[4], t1[4];
            ldm4(t0, stg + 2 * A_SZ + boff + kb);
            ldm4(t1, stg + 2 * A_SZ + boff + kb + 16 * LDS_EL * 2);
            bh[0][0] = t0[0]; bh[0][1] = t0[2]; bh[1][0] = t0[1]; bh[1][1] = t0[3];
            bh[2][0] = t1[0]; bh[2][1] = t1[2]; bh[3][0] = t1[1]; bh[3][1] = t1[3];
        }
        #pragma unroll
        for (int j = 0; j < 4; j++)
            #pragma unroll
            for (int i = 0; i < 4; i++) mma16(acc[i][j], ahi[i], bh[j]);   // hi*hi

        {
            uint32_t t0[4], t1[4], bl[4][2];
            ldm4(t0, stg + 3 * A_SZ + boff + kb);
            ldm4(t1, stg + 3 * A_SZ + boff + kb + 16 * LDS_EL * 2);
            bl[0][0] = t0[0]; bl[0][1] = t0[2]; bl[1][0] = t0[1]; bl[1][1] = t0[3];
            bl[2][0] = t1[0]; bl[2][1] = t1[2]; bl[3][0] = t1[1]; bl[3][1] = t1[3];
            #pragma unroll
            for (int j = 0; j < 4; j++)
                #pragma unroll
                for (int i = 0; i < 4; i++) mma16(acc[i][j], ahi[i], bl[j]); // hi*lo
        }
        {
            uint32_t alo[4][4];
            #pragma unroll
            for (int i = 0; i < 4; i++) ldm4(alo[i], stg + A_SZ + aoff + kb + i * (16 * LDS_EL * 2));
            #pragma unroll
            for (int j = 0; j < 4; j++)
                #pragma unroll
                for (int i = 0; i < 4; i++) mma16(acc[i][j], alo[i], bh[j]); // lo*hi
        }
    }
}

// ---------------- pipelined GEMM segment ----------------
__device__ __forceinline__ void gemm_pipe(
    const __nv_bfloat16* __restrict__ Ah, const __nv_bfloat16* __restrict__ Al, int lda, int m0,
    const __nv_bfloat16* __restrict__ Bh, const __nv_bfloat16* __restrict__ Bl, int ldb, int n0,
    int K, uint32_t sb, float acc[4][4][4])
{
    const int tid = threadIdx.x;
    const int warp = tid >> 5, lane = tid & 31;
    const int wr = warp >> 2, wc = warp & 3;

    const __nv_bfloat16* src0 = Ah + (size_t)m0 * lda;
    const __nv_bfloat16* src1 = Al + (size_t)m0 * lda;
    const __nv_bfloat16* src2 = Bh + (size_t)n0 * ldb;
    const __nv_bfloat16* src3 = Bl + (size_t)n0 * ldb;

    auto issue = [&](int slab, int buf) {
        const int k0 = slab * 32;
        const uint32_t db = sb + buf * STAGE;
        #pragma unroll
        for (int t = 0; t < 8; t++) {
            int id   = tid + t * 256;
            int tile = id >> 9;            // 512 16B-chunks per tile
            int c    = id & 511;
            int row  = c >> 2, seg = c & 3;
            const __nv_bfloat16* s;
            if      (tile == 0) s = src0 + (size_t)row * lda + k0 + seg * 8;
            else if (tile == 1) s = src1 + (size_t)row * lda + k0 + seg * 8;
            else if (tile == 2) s = src2 + (size_t)row * ldb + k0 + seg * 8;
            else                s = src3 + (size_t)row * ldb + k0 + seg * 8;
            cp16(db + tile * A_SZ + (row * LDS_EL + seg * 8) * 2, s);
        }
        CP_COMMIT();
    };

    const int nslab = K / 32;
    issue(0, 0);
    for (int s = 0; s < nslab; s++) {
        if (s + 1 < nslab) { issue(s + 1, (s + 1) & 1); CP_WAIT(1); }
        else               { CP_WAIT(0); }
        __syncthreads();
        compute_slab(sb + (s & 1) * STAGE, acc, wr, wc, lane);
        __syncthreads();
    }
}

// ---------------- kernels ----------------
__global__ void split_kernel(const float* __restrict__ src,
                             __nv_bfloat16* __restrict__ hi,
                             __nv_bfloat16* __restrict__ lo, int n)
{
    int i = (blockIdx.x * blockDim.x + threadIdx.x) * 4;
    if (i >= n) return;
    float4 v = *(const float4*)(src + i);
    __nv_bfloat16 h[4], l[4];
    h[0] = __float2bfloat16(v.x); l[0] = __float2bfloat16(v.x - __bfloat162float(h[0]));
    h[1] = __float2bfloat16(v.y); l[1] = __float2bfloat16(v.y - __bfloat162float(h[1]));
    h[2] = __float2bfloat16(v.z); l[2] = __float2bfloat16(v.z - __bfloat162float(h[2]));
    h[3] = __float2bfloat16(v.w); l[3] = __float2bfloat16(v.w - __bfloat162float(h[3]));
    *(uint2*)(hi + i) = *(uint2*)h;
    *(uint2*)(lo + i) = *(uint2*)l;
}

// clear chain flags (must run before scan_fused every launch/replay)
__global__ void clear_flags()
{
    g_flag[threadIdx.x] = 0;
}

__global__ __launch_bounds__(256, 2)
void proj_kernel(const float* __restrict__ bias)
{
    extern __shared__ char smem[];
    uint32_t sb = smem_u32(smem);
    float acc[4][4][4] = {};

    const int m0 = blockIdx.y * 128;
    const int bx = blockIdx.x;               // 0,1 -> a; 2,3 -> b
    const bool is_a = (bx < 2);
    const int n0 = (bx & 1) * 128;
    const __nv_bfloat16* Wh = is_a ? g_wahi : g_bwhi;
    const __nv_bfloat16* Wl = is_a ? g_walo : g_bwlo;

    gemm_pipe(g_xhi, g_xlo, DM, m0, Wh, Wl, DM, n0, DM, sb, acc);

    float* dst = is_a ? g_a : g_b;
    const int warp = threadIdx.x >> 5, lane = threadIdx.x & 31;
    const int wr = warp >> 2, wc = warp & 3;
    const int gq = lane >> 2, tq = lane & 3;

    #pragma unroll
    for (int i = 0; i < 4; i++) {
        #pragma unroll
        for (int j = 0; j < 4; j++) {
            const int row = m0 + wr * 64 + i * 16 + gq;
            const int col = n0 + wc * 32 + j * 8 + tq * 2;
            float v0 = acc[i][j][0], v1 = acc[i][j][1];
            float v2 = acc[i][j][2], v3 = acc[i][j][3];
            if (is_a) {
                float b0 = bias[col], b1 = bias[col + 1];
                v0 = 1.0f / (1.0f + __expf(-(v0 + b0)));
                v1 = 1.0f / (1.0f + __expf(-(v1 + b1)));
                v2 = 1.0f / (1.0f + __expf(-(v2 + b0)));
                v3 = 1.0f / (1.0f + __expf(-(v3 + b1)));
            }
            *(float2*)&dst[(size_t)row * NS + col]       = make_float2(v0, v1);
            *(float2*)&dst[(size_t)(row + 8) * NS + col] = make_float2(v2, v3);
        }
    }
}

__global__ __launch_bounds__(256, 2)
void out_kernel(float* __restrict__ Y)
{
    extern __shared__ char smem[];
    uint32_t sb = smem_u32(smem);
    float acc[4][4][4] = {};

    const int m0 = blockIdx.y * 128;
    const int n0 = blockIdx.x * 128;

    gemm_pipe(g_hhi, g_hlo, NS, m0, g_chi, g_clo, NS, n0, NS, sb, acc); // h @ C^T
    gemm_pipe(g_xhi, g_xlo, DM, m0, g_dhi, g_dlo, DM, n0, DM, sb, acc); // x @ D^T

    const int warp = threadIdx.x >> 5, lane = threadIdx.x & 31;
    const int wr = warp >> 2, wc = warp & 3;
    const int gq = lane >> 2, tq = lane & 3;

    #pragma unroll
    for (int i = 0; i < 4; i++) {
        #pragma unroll
        for (int j = 0; j < 4; j++) {
            const int row = m0 + wr * 64 + i * 16 + gq;
            const int col = n0 + wc * 32 + j * 8 + tq * 2;
            *(float2*)&Y[(size_t)row * DM + col]       = make_float2(acc[i][j][0], acc[i][j][1]);
            *(float2*)&Y[(size_t)(row + 8) * DM + col] = make_float2(acc[i][j][2], acc[i][j][3]);
        }
    }
}

// ---------------- single-pass chained scan (deterministic serial chain) ----------------
// Phase 1: local chunk aggregate (A, Bv) == old scan_agg arithmetic.
// Chain:   P_c = A_c * P_{c-1} + B_c   == old scan_carry arithmetic, same order.
// Phase 2: h_t = a_t * h_{t-1} + b_t from carry == old scan_apply (a/b hot in L2).
__global__ void scan_fused()
{
    const int bc = blockIdx.x, n = threadIdx.x;
    const int b = bc / NCHUNK, c = bc % NCHUNK;
    const size_t base = ((size_t)b * SEQ + (size_t)c * CHUNK) * NS + n;

    // phase 1: local aggregate
    float A = 1.0f, Bv = 0.0f;
    for (int s = 0; s < CHUNK; s++) {
        size_t idx = base + (size_t)s * NS;
        float a = g_a[idx], bb = g_b[idx];
        A  = a * A;
        Bv = a * Bv + bb;
    }

    // wait for predecessor's inclusive prefix
    float carry = 0.0f;
    if (c > 0) {
        if (threadIdx.x == 0) {
            while (atomicAdd(&g_flag[bc - 1], 0) == 0) { }
        }
        __syncthreads();
        __threadfence();                      // acquire: order payload reads after flag
        carry = g_pref[(size_t)(bc - 1) * NS + n];
    }

    // publish own inclusive prefix
    g_pref[(size_t)bc * NS + n] = A * carry + Bv;
    __threadfence();                          // release: payload before flag
    __syncthreads();
    if (threadIdx.x == 0) {
        __threadfence();
        atomicExch(&g_flag[bc], 1);
    }

    // phase 2: apply carry, write h (bf16 hi/lo)
    float h = carry;
    for (int s = 0; s < CHUNK; s++) {
        size_t idx = base + (size_t)s * NS;
        h = g_a[idx] * h + g_b[idx];
        __nv_bfloat16 hh = __float2bfloat16(h);
        g_hhi[idx] = hh;
        g_hlo[idx] = __float2bfloat16(h - __bfloat162float(hh));
    }
}

// ---------------- launch ----------------
extern "C" void kernel_launch(void* const* d_in, const int* in_sizes, int n_in,
                              void* d_out, int out_size)
{
    const float* x    = (const float*)d_in[0];
    const float* Wa_w = (const float*)d_in[1];
    const float* Wa_b = (const float*)d_in[2];
    const float* B_w  = (const float*)d_in[3];
    const float* C_w  = (const float*)d_in[4];
    const float* D_w  = (const float*)d_in[5];
    float* y = (float*)d_out;

    cudaFuncSetAttribute(proj_kernel, cudaFuncAttributeMaxDynamicSharedMemorySize, SMEM_TOTAL);
    cudaFuncSetAttribute(out_kernel,  cudaFuncAttributeMaxDynamicSharedMemorySize, SMEM_TOTAL);

    __nv_bfloat16 *xhi, *xlo, *wahi, *walo, *bwhi, *bwlo, *chi, *clo, *dhi, *dlo;
    cudaGetSymbolAddress((void**)&xhi,  g_xhi);  cudaGetSymbolAddress((void**)&xlo,  g_xlo);
    cudaGetSymbolAddress((void**)&wahi, g_wahi); cudaGetSymbolAddress((void**)&walo, g_walo);
    cudaGetSymbolAddress((void**)&bwhi, g_bwhi); cudaGetSymbolAddress((void**)&bwlo, g_bwlo);
    cudaGetSymbolAddress((void**)&chi,  g_chi);  cudaGetSymbolAddress((void**)&clo,  g_clo);
    cudaGetSymbolAddress((void**)&dhi,  g_dhi);  cudaGetSymbolAddress((void**)&dlo,  g_dlo);

    split_kernel<<<(M_ROWS*DM/4 + 255)/256, 256>>>(x,    xhi,  xlo,  M_ROWS*DM);
    split_kernel<<<(NS*DM/4     + 255)/256, 256>>>(Wa_w, wahi, walo, NS*DM);
    split_kernel<<<(NS*DM/4     + 255)/256, 256>>>(B_w,  bwhi, bwlo, NS*DM);
    split_kernel<<<(DM*NS/4     + 255)/256, 256>>>(C_w,  chi,  clo,  DM*NS);
    split_kernel<<<(DM*DM/4     + 255)/256, 256>>>(D_w,  dhi,  dlo,  DM*DM);
    clear_flags<<<1, BATCH * NCHUNK>>>();

    dim3 blk(256);
    dim3 gproj(4, M_ROWS / 128);          // n-block fastest -> A reuse in L2
    proj_kernel<<<gproj, blk, SMEM_TOTAL>>>(Wa_b);

    scan_fused<<<BATCH * NCHUNK, NS>>>();

    dim3 gout(DM / 128, M_ROWS / 128);    // n-block fastest -> A reuse in L2
    out_kernel<<<gout, blk, SMEM_TOTAL>>>(y);
}

// round 13
// speedup vs baseline: 1.0883x; 1.0883x over previous
#include <cuda_runtime.h>
#include <cuda_bf16.h>
#include <stdint.h>
#include <math.h>

// ---------------- problem constants ----------------
#define BATCH   8
#define SEQ     4096
#define DM      1024
#define NS      256
#define M_ROWS  (BATCH*SEQ)     // 32768
#define CHUNK   32
#define NCHUNK  (SEQ/CHUNK)     // 128

// ---------------- scratch ----------------
__device__ float g_a[M_ROWS * NS];
__device__ float g_b[M_ROWS * NS];
__device__ float g_Aagg[BATCH * NCHUNK * NS];
__device__ float g_Bagg[BATCH * NCHUNK * NS];
__device__ float g_carry[BATCH * NCHUNK * NS];

__device__ __nv_bfloat16 g_xhi[M_ROWS * DM], g_xlo[M_ROWS * DM];
__device__ __nv_bfloat16 g_hhi[M_ROWS * NS], g_hlo[M_ROWS * NS];
__device__ __nv_bfloat16 g_wahi[NS * DM],  g_walo[NS * DM];
__device__ __nv_bfloat16 g_bwhi[NS * DM],  g_bwlo[NS * DM];
__device__ __nv_bfloat16 g_chi[DM * NS],   g_clo[DM * NS];
__device__ __nv_bfloat16 g_dhi[DM * DM],   g_dlo[DM * DM];

// ---------------- GEMM config (128x128, 2 CTA/SM) ----------------
#define LDS_EL  40
#define A_SZ    (128 * LDS_EL * 2)      // 10240 B
#define STAGE   (4 * A_SZ)              // 40960 B
#define SMEM_TOTAL (2 * STAGE)          // 81920 B

// ---------------- PTX helpers ----------------
__device__ __forceinline__ uint32_t smem_u32(const void* p) {
    uint32_t a;
    asm("{ .reg .u64 t; cvta.to.shared.u64 t, %1; cvt.u32.u64 %0, t; }" : "=r"(a) : "l"(p));
    return a;
}
__device__ __forceinline__ void cp16(uint32_t d, const void* s) {
    asm volatile("cp.async.cg.shared.global [%0], [%1], 16;" :: "r"(d), "l"(s));
}
#define CP_COMMIT() asm volatile("cp.async.commit_group;" ::: "memory")
#define CP_WAIT(N)  asm volatile("cp.async.wait_group %0;" :: "n"(N) : "memory")

__device__ __forceinline__ void ldm4(uint32_t* r, uint32_t a) {
    asm volatile("ldmatrix.sync.aligned.m8n8.x4.shared.b16 {%0,%1,%2,%3}, [%4];"
        : "=r"(r[0]), "=r"(r[1]), "=r"(r[2]), "=r"(r[3]) : "r"(a));
}
__device__ __forceinline__ void mma16(float* c, const uint32_t* a, const uint32_t* b) {
    asm volatile("mma.sync.aligned.m16n8k16.row.col.f32.bf16.bf16.f32 "
        "{%0,%1,%2,%3}, {%4,%5,%6,%7}, {%8,%9}, {%0,%1,%2,%3};"
        : "+f"(c[0]), "+f"(c[1]), "+f"(c[2]), "+f"(c[3])
        : "r"(a[0]), "r"(a[1]), "r"(a[2]), "r"(a[3]), "r"(b[0]), "r"(b[1]));
}

// ---------------- per-slab compute: 3-pass bf16 compensation ----------------
__device__ __forceinline__ void compute_slab(uint32_t stg, float acc[4][4][4],
                                             int wr, int wc, int lane)
{
    const uint32_t aoff = ((wr * 64 + (lane & 15)) * LDS_EL + (lane >> 4) * 8) * 2;
    const uint32_t boff = ((wc * 32 + (lane & 15)) * LDS_EL + (lane >> 4) * 8) * 2;
    #pragma unroll
    for (int ks = 0; ks < 2; ks++) {
        const uint32_t kb = ks * 32;   // 16 bf16 = 32 B
        uint32_t ahi[4][4];
        #pragma unroll
        for (int i = 0; i < 4; i++) ldm4(ahi[i], stg + aoff + kb + i * (16 * LDS_EL * 2));

        uint32_t bh[4][2];
        {
            uint32_t t0[4], t1[4];
            ldm4(t0, stg + 2 * A_SZ + boff + kb);
            ldm4(t1, stg + 2 * A_SZ + boff + kb + 16 * LDS_EL * 2);
            bh[0][0] = t0[0]; bh[0][1] = t0[2]; bh[1][0] = t0[1]; bh[1][1] = t0[3];
            bh[2][0] = t1[0]; bh[2][1] = t1[2]; bh[3][0] = t1[1]; bh[3][1] = t1[3];
        }
        #pragma unroll
        for (int j = 0; j < 4; j++)
            #pragma unroll
            for (int i = 0; i < 4; i++) mma16(acc[i][j], ahi[i], bh[j]);   // hi*hi

        {
            uint32_t t0[4], t1[4], bl[4][2];
            ldm4(t0, stg + 3 * A_SZ + boff + kb);
            ldm4(t1, stg + 3 * A_SZ + boff + kb + 16 * LDS_EL * 2);
            bl[0][0] = t0[0]; bl[0][1] = t0[2]; bl[1][0] = t0[1]; bl[1][1] = t0[3];
            bl[2][0] = t1[0]; bl[2][1] = t1[2]; bl[3][0] = t1[1]; bl[3][1] = t1[3];
            #pragma unroll
            for (int j = 0; j < 4; j++)
                #pragma unroll
                for (int i = 0; i < 4; i++) mma16(acc[i][j], ahi[i], bl[j]); // hi*lo
        }
        {
            uint32_t alo[4][4];
            #pragma unroll
            for (int i = 0; i < 4; i++) ldm4(alo[i], stg + A_SZ + aoff + kb + i * (16 * LDS_EL * 2));
            #pragma unroll
            for (int j = 0; j < 4; j++)
                #pragma unroll
                for (int i = 0; i < 4; i++) mma16(acc[i][j], alo[i], bh[j]); // lo*hi
        }
    }
}

// ---------------- pipelined GEMM segment ----------------
__device__ __forceinline__ void gemm_pipe(
    const __nv_bfloat16* __restrict__ Ah, const __nv_bfloat16* __restrict__ Al, int lda, int m0,
    const __nv_bfloat16* __restrict__ Bh, const __nv_bfloat16* __restrict__ Bl, int ldb, int n0,
    int K, uint32_t sb, float acc[4][4][4])
{
    const int tid = threadIdx.x;
    const int warp = tid >> 5, lane = tid & 31;
    const int wr = warp >> 2, wc = warp & 3;

    const __nv_bfloat16* src0 = Ah + (size_t)m0 * lda;
    const __nv_bfloat16* src1 = Al + (size_t)m0 * lda;
    const __nv_bfloat16* src2 = Bh + (size_t)n0 * ldb;
    const __nv_bfloat16* src3 = Bl + (size_t)n0 * ldb;

    auto issue = [&](int slab, int buf) {
        const int k0 = slab * 32;
        const uint32_t db = sb + buf * STAGE;
        #pragma unroll
        for (int t = 0; t < 8; t++) {
            int id   = tid + t * 256;
            int tile = id >> 9;            // 512 16B-chunks per tile
            int c    = id & 511;
            int row  = c >> 2, seg = c & 3;
            const __nv_bfloat16* s;
            if      (tile == 0) s = src0 + (size_t)row * lda + k0 + seg * 8;
            else if (tile == 1) s = src1 + (size_t)row * lda + k0 + seg * 8;
            else if (tile == 2) s = src2 + (size_t)row * ldb + k0 + seg * 8;
            else                s = src3 + (size_t)row * ldb + k0 + seg * 8;
            cp16(db + tile * A_SZ + (row * LDS_EL + seg * 8) * 2, s);
        }
        CP_COMMIT();
    };

    const int nslab = K / 32;
    issue(0, 0);
    for (int s = 0; s < nslab; s++) {
        if (s + 1 < nslab) { issue(s + 1, (s + 1) & 1); CP_WAIT(1); }
        else               { CP_WAIT(0); }
        __syncthreads();
        compute_slab(sb + (s & 1) * STAGE, acc, wr, wc, lane);
        __syncthreads();
    }
}

// ---------------- kernels ----------------
__global__ void split_kernel(const float* __restrict__ src,
                             __nv_bfloat16* __restrict__ hi,
                             __nv_bfloat16* __restrict__ lo, int n)
{
    int i = (blockIdx.x * blockDim.x + threadIdx.x) * 4;
    if (i >= n) return;
    float4 v = *(const float4*)(src + i);
    __nv_bfloat16 h[4], l[4];
    h[0] = __float2bfloat16(v.x); l[0] = __float2bfloat16(v.x - __bfloat162float(h[0]));
    h[1] = __float2bfloat16(v.y); l[1] = __float2bfloat16(v.y - __bfloat162float(h[1]));
    h[2] = __float2bfloat16(v.z); l[2] = __float2bfloat16(v.z - __bfloat162float(h[2]));
    h[3] = __float2bfloat16(v.w); l[3] = __float2bfloat16(v.w - __bfloat162float(h[3]));
    *(uint2*)(hi + i) = *(uint2*)h;
    *(uint2*)(lo + i) = *(uint2*)l;
}

__global__ __launch_bounds__(256, 2)
void proj_kernel(const float* __restrict__ bias)
{
    extern __shared__ char smem[];
    uint32_t sb = smem_u32(smem);
    float acc[4][4][4] = {};

    const int m0 = blockIdx.y * 128;
    const int bx = blockIdx.x;               // 0,1 -> a; 2,3 -> b
    const bool is_a = (bx < 2);
    const int n0 = (bx & 1) * 128;
    const __nv_bfloat16* Wh = is_a ? g_wahi : g_bwhi;
    const __nv_bfloat16* Wl = is_a ? g_walo : g_bwlo;

    gemm_pipe(g_xhi, g_xlo, DM, m0, Wh, Wl, DM, n0, DM, sb, acc);

    float* dst = is_a ? g_a : g_b;
    const int warp = threadIdx.x >> 5, lane = threadIdx.x & 31;
    const int wr = warp >> 2, wc = warp & 3;
    const int gq = lane >> 2, tq = lane & 3;

    #pragma unroll
    for (int i = 0; i < 4; i++) {
        #pragma unroll
        for (int j = 0; j < 4; j++) {
            const int row = m0 + wr * 64 + i * 16 + gq;
            const int col = n0 + wc * 32 + j * 8 + tq * 2;
            float v0 = acc[i][j][0], v1 = acc[i][j][1];
            float v2 = acc[i][j][2], v3 = acc[i][j][3];
            if (is_a) {
                float b0 = bias[col], b1 = bias[col + 1];
                v0 = 1.0f / (1.0f + __expf(-(v0 + b0)));
                v1 = 1.0f / (1.0f + __expf(-(v1 + b1)));
                v2 = 1.0f / (1.0f + __expf(-(v2 + b0)));
                v3 = 1.0f / (1.0f + __expf(-(v3 + b1)));
            }
            *(float2*)&dst[(size_t)row * NS + col]       = make_float2(v0, v1);
            *(float2*)&dst[(size_t)(row + 8) * NS + col] = make_float2(v2, v3);
        }
    }
}

__global__ __launch_bounds__(256, 2)
void out_kernel(float* __restrict__ Y)
{
    extern __shared__ char smem[];
    uint32_t sb = smem_u32(smem);
    float acc[4][4][4] = {};

    const int m0 = blockIdx.y * 128;
    const int n0 = blockIdx.x * 128;

    gemm_pipe(g_hhi, g_hlo, NS, m0, g_chi, g_clo, NS, n0, NS, sb, acc); // h @ C^T
    gemm_pipe(g_xhi, g_xlo, DM, m0, g_dhi, g_dlo, DM, n0, DM, sb, acc); // x @ D^T

    const int warp = threadIdx.x >> 5, lane = threadIdx.x & 31;
    const int wr = warp >> 2, wc = warp & 3;
    const int gq = lane >> 2, tq = lane & 3;

    #pragma unroll
    for (int i = 0; i < 4; i++) {
        #pragma unroll
        for (int j = 0; j < 4; j++) {
            const int row = m0 + wr * 64 + i * 16 + gq;
            const int col = n0 + wc * 32 + j * 8 + tq * 2;
            *(float2*)&Y[(size_t)row * DM + col]       = make_float2(acc[i][j][0], acc[i][j][1]);
            *(float2*)&Y[(size_t)(row + 8) * DM + col] = make_float2(acc[i][j][2], acc[i][j][3]);
        }
    }
}

// ---------------- scan (re-chunked: CHUNK=32, 1024-block agg/apply) ----------------
__global__ void scan_agg()
{
    const int bc = blockIdx.x, n = threadIdx.x;
    const int b = bc / NCHUNK, c = bc % NCHUNK;
    size_t base = ((size_t)b * SEQ + (size_t)c * CHUNK) * NS + n;
    float A = 1.0f, Bv = 0.0f;
    #pragma unroll 8
    for (int s = 0; s < CHUNK; s++) {
        size_t idx = base + (size_t)s * NS;
        float a = g_a[idx], bb = g_b[idx];
        A = a * A; Bv = a * Bv + bb;
    }
    g_Aagg[(size_t)bc * NS + n] = A;
    g_Bagg[(size_t)bc * NS + n] = Bv;
}

// 128-step chain with group prefetch (8 pairs in flight per group)
__global__ void scan_carry()
{
    const int b = blockIdx.x, n = threadIdx.x;
    float h = 0.0f;
    for (int c = 0; c < NCHUNK; c += 8) {
        float A[8], Bv[8];
        #pragma unroll
        for (int j = 0; j < 8; j++) {
            size_t idx = ((size_t)b * NCHUNK + c + j) * NS + n;
            A[j]  = g_Aagg[idx];
            Bv[j] = g_Bagg[idx];
        }
        #pragma unroll
        for (int j = 0; j < 8; j++) {
            size_t idx = ((size_t)b * NCHUNK + c + j) * NS + n;
            g_carry[idx] = h;
            h = A[j] * h + Bv[j];
        }
    }
}

__global__ void scan_apply()
{
    const int bc = blockIdx.x, n = threadIdx.x;
    const int b = bc / NCHUNK, c = bc % NCHUNK;
    float h = g_carry[(size_t)bc * NS + n];
    size_t base = ((size_t)b * SEQ + (size_t)c * CHUNK) * NS + n;
    #pragma unroll 8
    for (int s = 0; s < CHUNK; s++) {
        size_t idx = base + (size_t)s * NS;
        h = g_a[idx] * h + g_b[idx];
        __nv_bfloat16 hh = __float2bfloat16(h);
        g_hhi[idx] = hh;
        g_hlo[idx] = __float2bfloat16(h - __bfloat162float(hh));
    }
}

// ---------------- launch ----------------
extern "C" void kernel_launch(void* const* d_in, const int* in_sizes, int n_in,
                              void* d_out, int out_size)
{
    const float* x    = (const float*)d_in[0];
    const float* Wa_w = (const float*)d_in[1];
    const float* Wa_b = (const float*)d_in[2];
    const float* B_w  = (const float*)d_in[3];
    const float* C_w  = (const float*)d_in[4];
    const float* D_w  = (const float*)d_in[5];
    float* y = (float*)d_out;

    cudaFuncSetAttribute(proj_kernel, cudaFuncAttributeMaxDynamicSharedMemorySize, SMEM_TOTAL);
    cudaFuncSetAttribute(out_kernel,  cudaFuncAttributeMaxDynamicSharedMemorySize, SMEM_TOTAL);

    __nv_bfloat16 *xhi, *xlo, *wahi, *walo, *bwhi, *bwlo, *chi, *clo, *dhi, *dlo;
    cudaGetSymbolAddress((void**)&xhi,  g_xhi);  cudaGetSymbolAddress((void**)&xlo,  g_xlo);
    cudaGetSymbolAddress((void**)&wahi, g_wahi); cudaGetSymbolAddress((void**)&walo, g_walo);
    cudaGetSymbolAddress((void**)&bwhi, g_bwhi); cudaGetSymbolAddress((void**)&bwlo, g_bwlo);
    cudaGetSymbolAddress((void**)&chi,  g_chi);  cudaGetSymbolAddress((void**)&clo,  g_clo);
    cudaGetSymbolAddress((void**)&dhi,  g_dhi);  cudaGetSymbolAddress((void**)&dlo,  g_dlo);

    split_kernel<<<(M_ROWS*DM/4 + 255)/256, 256>>>(x,    xhi,  xlo,  M_ROWS*DM);
    split_kernel<<<(NS*DM/4     + 255)/256, 256>>>(Wa_w, wahi, walo, NS*DM);
    split_kernel<<<(NS*DM/4     + 255)/256, 256>>>(B_w,  bwhi, bwlo, NS*DM);
    split_kernel<<<(DM*NS/4     + 255)/256, 256>>>(C_w,  chi,  clo,  DM*NS);
    split_kernel<<<(DM*DM/4     + 255)/256, 256>>>(D_w,  dhi,  dlo,  DM*DM);

    dim3 blk(256);
    dim3 gproj(4, M_ROWS / 128);          // n-block fastest -> A reuse in L2
    proj_kernel<<<gproj, blk, SMEM_TOTAL>>>(Wa_b);

    scan_agg  <<<BATCH * NCHUNK, NS>>>(); // 1024 blocks
    scan_carry<<<BATCH, NS>>>();
    scan_apply<<<BATCH * NCHUNK, NS>>>(); // 1024 blocks

    dim3 gout(DM / 128, M_ROWS / 128);    // n-block fastest -> A reuse in L2
    out_kernel<<<gout, blk, SMEM_TOTAL>>>(y);
}

// round 14
// speedup vs baseline: 1.0956x; 1.0067x over previous
#include <cuda_runtime.h>
#include <cuda_bf16.h>
#include <stdint.h>
#include <math.h>

// ---------------- problem constants ----------------
#define BATCH   8
#define SEQ     4096
#define DM      1024
#define NS      256
#define M_ROWS  (BATCH*SEQ)     // 32768
#define CHUNK   32
#define NCHUNK  (SEQ/CHUNK)     // 128

// ---------------- scratch ----------------
__device__ float g_a[M_ROWS * NS];
__device__ float g_b[M_ROWS * NS];
__device__ float g_Aagg[BATCH * NCHUNK * NS];
__device__ float g_Bagg[BATCH * NCHUNK * NS];
__device__ float g_carry[BATCH * NCHUNK * NS];

__device__ __nv_bfloat16 g_xhi[M_ROWS * DM], g_xlo[M_ROWS * DM];
__device__ __nv_bfloat16 g_hhi[M_ROWS * NS], g_hlo[M_ROWS * NS];
__device__ __nv_bfloat16 g_wahi[NS * DM],  g_walo[NS * DM];
__device__ __nv_bfloat16 g_bwhi[NS * DM],  g_bwlo[NS * DM];
__device__ __nv_bfloat16 g_chi[DM * NS],   g_clo[DM * NS];
__device__ __nv_bfloat16 g_dhi[DM * DM],   g_dlo[DM * DM];

// ---------------- GEMM config (128x128, 2 CTA/SM) ----------------
#define LDS_EL  40
#define A_SZ    (128 * LDS_EL * 2)      // 10240 B
#define STAGE   (4 * A_SZ)              // 40960 B
#define SMEM_TOTAL (2 * STAGE)          // 81920 B

// ---------------- PTX helpers ----------------
__device__ __forceinline__ uint32_t smem_u32(const void* p) {
    uint32_t a;
    asm("{ .reg .u64 t; cvta.to.shared.u64 t, %1; cvt.u32.u64 %0, t; }" : "=r"(a) : "l"(p));
    return a;
}
__device__ __forceinline__ void cp16(uint32_t d, const void* s) {
    asm volatile("cp.async.cg.shared.global [%0], [%1], 16;" :: "r"(d), "l"(s));
}
#define CP_COMMIT() asm volatile("cp.async.commit_group;" ::: "memory")
#define CP_WAIT(N)  asm volatile("cp.async.wait_group %0;" :: "n"(N) : "memory")

__device__ __forceinline__ void ldm4(uint32_t* r, uint32_t a) {
    asm volatile("ldmatrix.sync.aligned.m8n8.x4.shared.b16 {%0,%1,%2,%3}, [%4];"
        : "=r"(r[0]), "=r"(r[1]), "=r"(r[2]), "=r"(r[3]) : "r"(a));
}
__device__ __forceinline__ void mma16(float* c, const uint32_t* a, const uint32_t* b) {
    asm volatile("mma.sync.aligned.m16n8k16.row.col.f32.bf16.bf16.f32 "
        "{%0,%1,%2,%3}, {%4,%5,%6,%7}, {%8,%9}, {%0,%1,%2,%3};"
        : "+f"(c[0]), "+f"(c[1]), "+f"(c[2]), "+f"(c[3])
        : "r"(a[0]), "r"(a[1]), "r"(a[2]), "r"(a[3]), "r"(b[0]), "r"(b[1]));
}

// ---------------- per-slab compute: 3-pass bf16 compensation ----------------
__device__ __forceinline__ void compute_slab(uint32_t stg, float acc[4][4][4],
                                             int wr, int wc, int lane)
{
    const uint32_t aoff = ((wr * 64 + (lane & 15)) * LDS_EL + (lane >> 4) * 8) * 2;
    const uint32_t boff = ((wc * 32 + (lane & 15)) * LDS_EL + (lane >> 4) * 8) * 2;
    #pragma unroll
    for (int ks = 0; ks < 2; ks++) {
        const uint32_t kb = ks * 32;   // 16 bf16 = 32 B
        uint32_t ahi[4][4];
        #pragma unroll
        for (int i = 0; i < 4; i++) ldm4(ahi[i], stg + aoff + kb + i * (16 * LDS_EL * 2));

        uint32_t bh[4][2];
        {
            uint32_t t0[4], t1[4];
            ldm4(t0, stg + 2 * A_SZ + boff + kb);
            ldm4(t1, stg + 2 * A_SZ + boff + kb + 16 * LDS_EL * 2);
            bh[0][0] = t0[0]; bh[0][1] = t0[2]; bh[1][0] = t0[1]; bh[1][1] = t0[3];
            bh[2][0] = t1[0]; bh[2][1] = t1[2]; bh[3][0] = t1[1]; bh[3][1] = t1[3];
        }
        #pragma unroll
        for (int j = 0; j < 4; j++)
            #pragma unroll
            for (int i = 0; i < 4; i++) mma16(acc[i][j], ahi[i], bh[j]);   // hi*hi

        {
            uint32_t t0[4], t1[4], bl[4][2];
            ldm4(t0, stg + 3 * A_SZ + boff + kb);
            ldm4(t1, stg + 3 * A_SZ + boff + kb + 16 * LDS_EL * 2);
            bl[0][0] = t0[0]; bl[0][1] = t0[2]; bl[1][0] = t0[1]; bl[1][1] = t0[3];
            bl[2][0] = t1[0]; bl[2][1] = t1[2]; bl[3][0] = t1[1]; bl[3][1] = t1[3];
            #pragma unroll
            for (int j = 0; j < 4; j++)
                #pragma unroll
                for (int i = 0; i < 4; i++) mma16(acc[i][j], ahi[i], bl[j]); // hi*lo
        }
        {
            uint32_t alo[4][4];
            #pragma unroll
            for (int i = 0; i < 4; i++) ldm4(alo[i], stg + A_SZ + aoff + kb + i * (16 * LDS_EL * 2));
            #pragma unroll
            for (int j = 0; j < 4; j++)
                #pragma unroll
                for (int i = 0; i < 4; i++) mma16(acc[i][j], alo[i], bh[j]); // lo*hi
        }
    }
}

// ---------------- pipelined GEMM segment (single sync per slab) ----------------
// Safety: the barrier at the end of iteration s-1 guarantees every warp finished
// compute(s-1) -- the previous occupant of buffer (s+1)&1 -- before any warp
// issues slab s+1 into that buffer at iteration s.
__device__ __forceinline__ void gemm_pipe(
    const __nv_bfloat16* __restrict__ Ah, const __nv_bfloat16* __restrict__ Al, int lda, int m0,
    const __nv_bfloat16* __restrict__ Bh, const __nv_bfloat16* __restrict__ Bl, int ldb, int n0,
    int K, uint32_t sb, float acc[4][4][4])
{
    const int tid = threadIdx.x;
    const int warp = tid >> 5, lane = tid & 31;
    const int wr = warp >> 2, wc = warp & 3;

    const __nv_bfloat16* src0 = Ah + (size_t)m0 * lda;
    const __nv_bfloat16* src1 = Al + (size_t)m0 * lda;
    const __nv_bfloat16* src2 = Bh + (size_t)n0 * ldb;
    const __nv_bfloat16* src3 = Bl + (size_t)n0 * ldb;

    auto issue = [&](int slab, int buf) {
        const int k0 = slab * 32;
        const uint32_t db = sb + buf * STAGE;
        #pragma unroll
        for (int t = 0; t < 8; t++) {
            int id   = tid + t * 256;
            int tile = id >> 9;            // 512 16B-chunks per tile
            int c    = id & 511;
            int row  = c >> 2, seg = c & 3;
            const __nv_bfloat16* s;
            if      (tile == 0) s = src0 + (size_t)row * lda + k0 + seg * 8;
            else if (tile == 1) s = src1 + (size_t)row * lda + k0 + seg * 8;
            else if (tile == 2) s = src2 + (size_t)row * ldb + k0 + seg * 8;
            else                s = src3 + (size_t)row * ldb + k0 + seg * 8;
            cp16(db + tile * A_SZ + (row * LDS_EL + seg * 8) * 2, s);
        }
        CP_COMMIT();
    };

    const int nslab = K / 32;
    issue(0, 0);
    CP_WAIT(0);
    __syncthreads();
    for (int s = 0; s < nslab; s++) {
        if (s + 1 < nslab) issue(s + 1, (s + 1) & 1);   // overlaps compute(s)
        compute_slab(sb + (s & 1) * STAGE, acc, wr, wc, lane);
        if (s + 1 < nslab) {
            CP_WAIT(0);            // slab s+1 loads landed
            __syncthreads();       // visible to all warps; also closes compute(s)
        }
    }
    __syncthreads();               // close last slab before buffer reuse / epilogue
}

// ---------------- kernels ----------------
__global__ void split_kernel(const float* __restrict__ src,
                             __nv_bfloat16* __restrict__ hi,
                             __nv_bfloat16* __restrict__ lo, int n)
{
    int i = (blockIdx.x * blockDim.x + threadIdx.x) * 4;
    if (i >= n) return;
    float4 v = *(const float4*)(src + i);
    __nv_bfloat16 h[4], l[4];
    h[0] = __float2bfloat16(v.x); l[0] = __float2bfloat16(v.x - __bfloat162float(h[0]));
    h[1] = __float2bfloat16(v.y); l[1] = __float2bfloat16(v.y - __bfloat162float(h[1]));
    h[2] = __float2bfloat16(v.z); l[2] = __float2bfloat16(v.z - __bfloat162float(h[2]));
    h[3] = __float2bfloat16(v.w); l[3] = __float2bfloat16(v.w - __bfloat162float(h[3]));
    *(uint2*)(hi + i) = *(uint2*)h;
    *(uint2*)(lo + i) = *(uint2*)l;
}

__global__ __launch_bounds__(256, 2)
void proj_kernel(const float* __restrict__ bias)
{
    extern __shared__ char smem[];
    uint32_t sb = smem_u32(smem);
    float acc[4][4][4] = {};

    const int m0 = blockIdx.y * 128;
    const int bx = blockIdx.x;               // 0,1 -> a; 2,3 -> b
    const bool is_a = (bx < 2);
    const int n0 = (bx & 1) * 128;
    const __nv_bfloat16* Wh = is_a ? g_wahi : g_bwhi;
    const __nv_bfloat16* Wl = is_a ? g_walo : g_bwlo;

    gemm_pipe(g_xhi, g_xlo, DM, m0, Wh, Wl, DM, n0, DM, sb, acc);

    float* dst = is_a ? g_a : g_b;
    const int warp = threadIdx.x >> 5, lane = threadIdx.x & 31;
    const int wr = warp >> 2, wc = warp & 3;
    const int gq = lane >> 2, tq = lane & 3;

    #pragma unroll
    for (int i = 0; i < 4; i++) {
        #pragma unroll
        for (int j = 0; j < 4; j++) {
            const int row = m0 + wr * 64 + i * 16 + gq;
            const int col = n0 + wc * 32 + j * 8 + tq * 2;
            float v0 = acc[i][j][0], v1 = acc[i][j][1];
            float v2 = acc[i][j][2], v3 = acc[i][j][3];
            if (is_a) {
                float b0 = bias[col], b1 = bias[col + 1];
                v0 = 1.0f / (1.0f + __expf(-(v0 + b0)));
                v1 = 1.0f / (1.0f + __expf(-(v1 + b1)));
                v2 = 1.0f / (1.0f + __expf(-(v2 + b0)));
                v3 = 1.0f / (1.0f + __expf(-(v3 + b1)));
            }
            *(float2*)&dst[(size_t)row * NS + col]       = make_float2(v0, v1);
            *(float2*)&dst[(size_t)(row + 8) * NS + col] = make_float2(v2, v3);
        }
    }
}

__global__ __launch_bounds__(256, 2)
void out_kernel(float* __restrict__ Y)
{
    extern __shared__ char smem[];
    uint32_t sb = smem_u32(smem);
    float acc[4][4][4] = {};

    const int m0 = blockIdx.y * 128;
    const int n0 = blockIdx.x * 128;

    gemm_pipe(g_hhi, g_hlo, NS, m0, g_chi, g_clo, NS, n0, NS, sb, acc); // h @ C^T
    gemm_pipe(g_xhi, g_xlo, DM, m0, g_dhi, g_dlo, DM, n0, DM, sb, acc); // x @ D^T

    const int warp = threadIdx.x >> 5, lane = threadIdx.x & 31;
    const int wr = warp >> 2, wc = warp & 3;
    const int gq = lane >> 2, tq = lane & 3;

    #pragma unroll
    for (int i = 0; i < 4; i++) {
        #pragma unroll
        for (int j = 0; j < 4; j++) {
            const int row = m0 + wr * 64 + i * 16 + gq;
            const int col = n0 + wc * 32 + j * 8 + tq * 2;
            *(float2*)&Y[(size_t)row * DM + col]       = make_float2(acc[i][j][0], acc[i][j][1]);
            *(float2*)&Y[(size_t)(row + 8) * DM + col] = make_float2(acc[i][j][2], acc[i][j][3]);
        }
    }
}

// ---------------- scan (CHUNK=32, 1024-block agg/apply) ----------------
__global__ void scan_agg()
{
    const int bc = blockIdx.x, n = threadIdx.x;
    const int b = bc / NCHUNK, c = bc % NCHUNK;
    size_t base = ((size_t)b * SEQ + (size_t)c * CHUNK) * NS + n;
    float A = 1.0f, Bv = 0.0f;
    #pragma unroll 8
    for (int s = 0; s < CHUNK; s++) {
        size_t idx = base + (size_t)s * NS;
        float a = g_a[idx], bb = g_b[idx];
        A = a * A; Bv = a * Bv + bb;
    }
    g_Aagg[(size_t)bc * NS + n] = A;
    g_Bagg[(size_t)bc * NS + n] = Bv;
}

__global__ void scan_carry()
{
    const int b = blockIdx.x, n = threadIdx.x;
    float h = 0.0f;
    for (int c = 0; c < NCHUNK; c += 8) {
        float A[8], Bv[8];
        #pragma unroll
        for (int j = 0; j < 8; j++) {
            size_t idx = ((size_t)b * NCHUNK + c + j) * NS + n;
            A[j]  = g_Aagg[idx];
            Bv[j] = g_Bagg[idx];
        }
        #pragma unroll
        for (int j = 0; j < 8; j++) {
            size_t idx = ((size_t)b * NCHUNK + c + j) * NS + n;
            g_carry[idx] = h;
            h = A[j] * h + Bv[j];
        }
    }
}

__global__ void scan_apply()
{
    const int bc = blockIdx.x, n = threadIdx.x;
    const int b = bc / NCHUNK, c = bc % NCHUNK;
    float h = g_carry[(size_t)bc * NS + n];
    size_t base = ((size_t)b * SEQ + (size_t)c * CHUNK) * NS + n;
    #pragma unroll 8
    for (int s = 0; s < CHUNK; s++) {
        size_t idx = base + (size_t)s * NS;
        h = g_a[idx] * h + g_b[idx];
        __nv_bfloat16 hh = __float2bfloat16(h);
        g_hhi[idx] = hh;
        g_hlo[idx] = __float2bfloat16(h - __bfloat162float(hh));
    }
}

// ---------------- launch ----------------
extern "C" void kernel_launch(void* const* d_in, const int* in_sizes, int n_in,
                              void* d_out, int out_size)
{
    const float* x    = (const float*)d_in[0];
    const float* Wa_w = (const float*)d_in[1];
    const float* Wa_b = (const float*)d_in[2];
    const float* B_w  = (const float*)d_in[3];
    const float* C_w  = (const float*)d_in[4];
    const float* D_w  = (const float*)d_in[5];
    float* y = (float*)d_out;

    cudaFuncSetAttribute(proj_kernel, cudaFuncAttributeMaxDynamicSharedMemorySize, SMEM_TOTAL);
    cudaFuncSetAttribute(out_kernel,  cudaFuncAttributeMaxDynamicSharedMemorySize, SMEM_TOTAL);

    __nv_bfloat16 *xhi, *xlo, *wahi, *walo, *bwhi, *bwlo, *chi, *clo, *dhi, *dlo;
    cudaGetSymbolAddress((void**)&xhi,  g_xhi);  cudaGetSymbolAddress((void**)&xlo,  g_xlo);
    cudaGetSymbolAddress((void**)&wahi, g_wahi); cudaGetSymbolAddress((void**)&walo, g_walo);
    cudaGetSymbolAddress((void**)&bwhi, g_bwhi); cudaGetSymbolAddress((void**)&bwlo, g_bwlo);
    cudaGetSymbolAddress((void**)&chi,  g_chi);  cudaGetSymbolAddress((void**)&clo,  g_clo);
    cudaGetSymbolAddress((void**)&dhi,  g_dhi);  cudaGetSymbolAddress((void**)&dlo,  g_dlo);

    split_kernel<<<(M_ROWS*DM/4 + 255)/256, 256>>>(x,    xhi,  xlo,  M_ROWS*DM);
    split_kernel<<<(NS*DM/4     + 255)/256, 256>>>(Wa_w, wahi, walo, NS*DM);
    split_kernel<<<(NS*DM/4     + 255)/256, 256>>>(B_w,  bwhi, bwlo, NS*DM);
    split_kernel<<<(DM*NS/4     + 255)/256, 256>>>(C_w,  chi,  clo,  DM*NS);
    split_kernel<<<(DM*DM/4     + 255)/256, 256>>>(D_w,  dhi,  dlo,  DM*DM);

    dim3 blk(256);
    dim3 gproj(4, M_ROWS / 128);          // n-block fastest -> A reuse in L2
    proj_kernel<<<gproj, blk, SMEM_TOTAL>>>(Wa_b);

    scan_agg  <<<BATCH * NCHUNK, NS>>>(); // 1024 blocks
    scan_carry<<<BATCH, NS>>>();
    scan_apply<<<BATCH * NCHUNK, NS>>>(); // 1024 blocks

    dim3 gout(DM / 128, M_ROWS / 128);    // n-block fastest -> A reuse in L2
    out_kernel<<<gout, blk, SMEM_TOTAL>>>(y);
}

// round 15
// speedup vs baseline: 1.1014x; 1.0053x over previous
#include <cuda_runtime.h>
#include <cuda_bf16.h>
#include <stdint.h>
#include <math.h>

// ---------------- problem constants ----------------
#define BATCH   8
#define SEQ     4096
#define DM      1024
#define NS      256
#define M_ROWS  (BATCH*SEQ)     // 32768
#define CHUNK   32
#define NCHUNK  (SEQ/CHUNK)     // 128

// ---------------- scratch ----------------
__device__ float g_a[M_ROWS * NS];
__device__ float g_b[M_ROWS * NS];
__device__ float g_Aagg[BATCH * NCHUNK * NS];
__device__ float g_Bagg[BATCH * NCHUNK * NS];
__device__ float g_carry[BATCH * NCHUNK * NS];

__device__ __nv_bfloat16 g_xhi[M_ROWS * DM], g_xlo[M_ROWS * DM];
__device__ __nv_bfloat16 g_hhi[M_ROWS * NS], g_hlo[M_ROWS * NS];
__device__ __nv_bfloat16 g_wahi[NS * DM],  g_walo[NS * DM];
__device__ __nv_bfloat16 g_bwhi[NS * DM],  g_bwlo[NS * DM];
__device__ __nv_bfloat16 g_chi[DM * NS],   g_clo[DM * NS];
__device__ __nv_bfloat16 g_dhi[DM * DM],   g_dlo[DM * DM];

// ---------------- GEMM config (128x128, 2 CTA/SM) ----------------
#define LDS_EL  40
#define A_SZ    (128 * LDS_EL * 2)      // 10240 B
#define STAGE   (4 * A_SZ)              // 40960 B
#define SMEM_TOTAL (2 * STAGE)          // 81920 B

// ---------------- PTX helpers ----------------
__device__ __forceinline__ uint32_t smem_u32(const void* p) {
    uint32_t a;
    asm("{ .reg .u64 t; cvta.to.shared.u64 t, %1; cvt.u32.u64 %0, t; }" : "=r"(a) : "l"(p));
    return a;
}
__device__ __forceinline__ void cp16(uint32_t d, const void* s) {
    asm volatile("cp.async.cg.shared.global [%0], [%1], 16;" :: "r"(d), "l"(s));
}
#define CP_COMMIT() asm volatile("cp.async.commit_group;" ::: "memory")
#define CP_WAIT(N)  asm volatile("cp.async.wait_group %0;" :: "n"(N) : "memory")

__device__ __forceinline__ void ldm4(uint32_t* r, uint32_t a) {
    asm volatile("ldmatrix.sync.aligned.m8n8.x4.shared.b16 {%0,%1,%2,%3}, [%4];"
        : "=r"(r[0]), "=r"(r[1]), "=r"(r[2]), "=r"(r[3]) : "r"(a));
}
__device__ __forceinline__ void mma16(float* c, const uint32_t* a, const uint32_t* b) {
    asm volatile("mma.sync.aligned.m16n8k16.row.col.f32.bf16.bf16.f32 "
        "{%0,%1,%2,%3}, {%4,%5,%6,%7}, {%8,%9}, {%0,%1,%2,%3};"
        : "+f"(c[0]), "+f"(c[1]), "+f"(c[2]), "+f"(c[3])
        : "r"(a[0]), "r"(a[1]), "r"(a[2]), "r"(a[3]), "r"(b[0]), "r"(b[1]));
}

// ---------------- per-slab compute: 3-pass bf16 compensation ----------------
__device__ __forceinline__ void compute_slab(uint32_t stg, float acc[4][4][4],
                                             int wr, int wc, int lane)
{
    const uint32_t aoff = ((wr * 64 + (lane & 15)) * LDS_EL + (lane >> 4) * 8) * 2;
    const uint32_t boff = ((wc * 32 + (lane & 15)) * LDS_EL + (lane >> 4) * 8) * 2;
    #pragma unroll
    for (int ks = 0; ks < 2; ks++) {
        const uint32_t kb = ks * 32;   // 16 bf16 = 32 B
        uint32_t ahi[4][4];
        #pragma unroll
        for (int i = 0; i < 4; i++) ldm4(ahi[i], stg + aoff + kb + i * (16 * LDS_EL * 2));

        uint32_t bh[4][2];
        {
            uint32_t t0[4], t1[4];
            ldm4(t0, stg + 2 * A_SZ + boff + kb);
            ldm4(t1, stg + 2 * A_SZ + boff + kb + 16 * LDS_EL * 2);
            bh[0][0] = t0[0]; bh[0][1] = t0[2]; bh[1][0] = t0[1]; bh[1][1] = t0[3];
            bh[2][0] = t1[0]; bh[2][1] = t1[2]; bh[3][0] = t1[1]; bh[3][1] = t1[3];
        }
        #pragma unroll
        for (int j = 0; j < 4; j++)
            #pragma unroll
            for (int i = 0; i < 4; i++) mma16(acc[i][j], ahi[i], bh[j]);   // hi*hi

        {
            uint32_t t0[4], t1[4], bl[4][2];
            ldm4(t0, stg + 3 * A_SZ + boff + kb);
            ldm4(t1, stg + 3 * A_SZ + boff + kb + 16 * LDS_EL * 2);
            bl[0][0] = t0[0]; bl[0][1] = t0[2]; bl[1][0] = t0[1]; bl[1][1] = t0[3];
            bl[2][0] = t1[0]; bl[2][1] = t1[2]; bl[3][0] = t1[1]; bl[3][1] = t1[3];
            #pragma unroll
            for (int j = 0; j < 4; j++)
                #pragma unroll
                for (int i = 0; i < 4; i++) mma16(acc[i][j], ahi[i], bl[j]); // hi*lo
        }
        {
            uint32_t alo[4][4];
            #pragma unroll
            for (int i = 0; i < 4; i++) ldm4(alo[i], stg + A_SZ + aoff + kb + i * (16 * LDS_EL * 2));
            #pragma unroll
            for (int j = 0; j < 4; j++)
                #pragma unroll
                for (int i = 0; i < 4; i++) mma16(acc[i][j], alo[i], bh[j]); // lo*hi
        }
    }
}

// ---------------- pipelined GEMM segment (single sync per slab) ----------------
__device__ __forceinline__ void gemm_pipe(
    const __nv_bfloat16* __restrict__ Ah, const __nv_bfloat16* __restrict__ Al, int lda, int m0,
    const __nv_bfloat16* __restrict__ Bh, const __nv_bfloat16* __restrict__ Bl, int ldb, int n0,
    int K, uint32_t sb, float acc[4][4][4])
{
    const int tid = threadIdx.x;
    const int warp = tid >> 5, lane = tid & 31;
    const int wr = warp >> 2, wc = warp & 3;

    const __nv_bfloat16* src0 = Ah + (size_t)m0 * lda;
    const __nv_bfloat16* src1 = Al + (size_t)m0 * lda;
    const __nv_bfloat16* src2 = Bh + (size_t)n0 * ldb;
    const __nv_bfloat16* src3 = Bl + (size_t)n0 * ldb;

    auto issue = [&](int slab, int buf) {
        const int k0 = slab * 32;
        const uint32_t db = sb + buf * STAGE;
        #pragma unroll
        for (int t = 0; t < 8; t++) {
            int id   = tid + t * 256;
            int tile = id >> 9;            // 512 16B-chunks per tile
            int c    = id & 511;
            int row  = c >> 2, seg = c & 3;
            const __nv_bfloat16* s;
            if      (tile == 0) s = src0 + (size_t)row * lda + k0 + seg * 8;
            else if (tile == 1) s = src1 + (size_t)row * lda + k0 + seg * 8;
            else if (tile == 2) s = src2 + (size_t)row * ldb + k0 + seg * 8;
            else                s = src3 + (size_t)row * ldb + k0 + seg * 8;
            cp16(db + tile * A_SZ + (row * LDS_EL + seg * 8) * 2, s);
        }
        CP_COMMIT();
    };

    const int nslab = K / 32;
    issue(0, 0);
    CP_WAIT(0);
    __syncthreads();
    for (int s = 0; s < nslab; s++) {
        if (s + 1 < nslab) issue(s + 1, (s + 1) & 1);   // overlaps compute(s)
        compute_slab(sb + (s & 1) * STAGE, acc, wr, wc, lane);
        if (s + 1 < nslab) {
            CP_WAIT(0);
            __syncthreads();
        }
    }
    __syncthreads();
}

// ---------------- fused split of all 5 f32 tensors -> bf16 hi/lo ----------------
#define F4_X   8388608u                    // M_ROWS*DM/4
#define F4_W   65536u                      // NS*DM/4 (== DM*NS/4)
#define F4_D   262144u                     // DM*DM/4
#define F4_TOT (F4_X + 3*F4_W + F4_D)      // 8847360 (divisible by 256)

__global__ void split_all(const float* __restrict__ x,  const float* __restrict__ wa,
                          const float* __restrict__ bw, const float* __restrict__ cw,
                          const float* __restrict__ dw)
{
    uint32_t id = blockIdx.x * blockDim.x + threadIdx.x;   // one float4
    const float* src; __nv_bfloat16 *hi, *lo; uint32_t off;
    if      (id < F4_X)          { src = x;  hi = g_xhi;  lo = g_xlo;  off = id; }
    else if (id < F4_X + F4_W)   { src = wa; hi = g_wahi; lo = g_walo; off = id - F4_X; }
    else if (id < F4_X + 2*F4_W) { src = bw; hi = g_bwhi; lo = g_bwlo; off = id - (F4_X + F4_W); }
    else if (id < F4_X + 3*F4_W) { src = cw; hi = g_chi;  lo = g_clo;  off = id - (F4_X + 2*F4_W); }
    else                         { src = dw; hi = g_dhi;  lo = g_dlo;  off = id - (F4_X + 3*F4_W); }

    size_t i = (size_t)off * 4;
    float4 v = *(const float4*)(src + i);
    __nv_bfloat16 h[4], l[4];
    h[0] = __float2bfloat16(v.x); l[0] = __float2bfloat16(v.x - __bfloat162float(h[0]));
    h[1] = __float2bfloat16(v.y); l[1] = __float2bfloat16(v.y - __bfloat162float(h[1]));
    h[2] = __float2bfloat16(v.z); l[2] = __float2bfloat16(v.z - __bfloat162float(h[2]));
    h[3] = __float2bfloat16(v.w); l[3] = __float2bfloat16(v.w - __bfloat162float(h[3]));
    *(uint2*)(hi + i) = *(uint2*)h;
    *(uint2*)(lo + i) = *(uint2*)l;
}

__global__ __launch_bounds__(256, 2)
void proj_kernel(const float* __restrict__ bias)
{
    extern __shared__ char smem[];
    uint32_t sb = smem_u32(smem);
    float acc[4][4][4] = {};

    const int m0 = blockIdx.y * 128;
    const int bx = blockIdx.x;               // 0,1 -> a; 2,3 -> b
    const bool is_a = (bx < 2);
    const int n0 = (bx & 1) * 128;
    const __nv_bfloat16* Wh = is_a ? g_wahi : g_bwhi;
    const __nv_bfloat16* Wl = is_a ? g_walo : g_bwlo;

    gemm_pipe(g_xhi, g_xlo, DM, m0, Wh, Wl, DM, n0, DM, sb, acc);

    float* dst = is_a ? g_a : g_b;
    const int warp = threadIdx.x >> 5, lane = threadIdx.x & 31;
    const int wr = warp >> 2, wc = warp & 3;
    const int gq = lane >> 2, tq = lane & 3;

    #pragma unroll
    for (int i = 0; i < 4; i++) {
        #pragma unroll
        for (int j = 0; j < 4; j++) {
            const int row = m0 + wr * 64 + i * 16 + gq;
            const int col = n0 + wc * 32 + j * 8 + tq * 2;
            float v0 = acc[i][j][0], v1 = acc[i][j][1];
            float v2 = acc[i][j][2], v3 = acc[i][j][3];
            if (is_a) {
                float b0 = bias[col], b1 = bias[col + 1];
                v0 = 1.0f / (1.0f + __expf(-(v0 + b0)));
                v1 = 1.0f / (1.0f + __expf(-(v1 + b1)));
                v2 = 1.0f / (1.0f + __expf(-(v2 + b0)));
                v3 = 1.0f / (1.0f + __expf(-(v3 + b1)));
            }
            *(float2*)&dst[(size_t)row * NS + col]       = make_float2(v0, v1);
            *(float2*)&dst[(size_t)(row + 8) * NS + col] = make_float2(v2, v3);
        }
    }
}

__global__ __launch_bounds__(256, 2)
void out_kernel(float* __restrict__ Y)
{
    extern __shared__ char smem[];
    uint32_t sb = smem_u32(smem);
    float acc[4][4][4] = {};

    const int m0 = blockIdx.y * 128;
    const int n0 = blockIdx.x * 128;

    gemm_pipe(g_hhi, g_hlo, NS, m0, g_chi, g_clo, NS, n0, NS, sb, acc); // h @ C^T
    gemm_pipe(g_xhi, g_xlo, DM, m0, g_dhi, g_dlo, DM, n0, DM, sb, acc); // x @ D^T

    const int warp = threadIdx.x >> 5, lane = threadIdx.x & 31;
    const int wr = warp >> 2, wc = warp & 3;
    const int gq = lane >> 2, tq = lane & 3;

    #pragma unroll
    for (int i = 0; i < 4; i++) {
        #pragma unroll
        for (int j = 0; j < 4; j++) {
            const int row = m0 + wr * 64 + i * 16 + gq;
            const int col = n0 + wc * 32 + j * 8 + tq * 2;
            *(float2*)&Y[(size_t)row * DM + col]       = make_float2(acc[i][j][0], acc[i][j][1]);
            *(float2*)&Y[(size_t)(row + 8) * DM + col] = make_float2(acc[i][j][2], acc[i][j][3]);
        }
    }
}

// ---------------- scan (CHUNK=32, 1024-block agg/apply) ----------------
__global__ void scan_agg()
{
    const int bc = blockIdx.x, n = threadIdx.x;
    const int b = bc / NCHUNK, c = bc % NCHUNK;
    size_t base = ((size_t)b * SEQ + (size_t)c * CHUNK) * NS + n;
    float A = 1.0f, Bv = 0.0f;
    #pragma unroll 8
    for (int s = 0; s < CHUNK; s++) {
        size_t idx = base + (size_t)s * NS;
        float a = g_a[idx], bb = g_b[idx];
        A = a * A; Bv = a * Bv + bb;
    }
    g_Aagg[(size_t)bc * NS + n] = A;
    g_Bagg[(size_t)bc * NS + n] = Bv;
}

__global__ void scan_carry()
{
    const int b = blockIdx.x, n = threadIdx.x;
    float h = 0.0f;
    for (int c = 0; c < NCHUNK; c += 8) {
        float A[8], Bv[8];
        #pragma unroll
        for (int j = 0; j < 8; j++) {
            size_t idx = ((size_t)b * NCHUNK + c + j) * NS + n;
            A[j]  = g_Aagg[idx];
            Bv[j] = g_Bagg[idx];
        }
        #pragma unroll
        for (int j = 0; j < 8; j++) {
            size_t idx = ((size_t)b * NCHUNK + c + j) * NS + n;
            g_carry[idx] = h;
            h = A[j] * h + Bv[j];
        }
    }
}

__global__ void scan_apply()
{
    const int bc = blockIdx.x, n = threadIdx.x;
    const int b = bc / NCHUNK, c = bc % NCHUNK;
    float h = g_carry[(size_t)bc * NS + n];
    size_t base = ((size_t)b * SEQ + (size_t)c * CHUNK) * NS + n;
    #pragma unroll 8
    for (int s = 0; s < CHUNK; s++) {
        size_t idx = base + (size_t)s * NS;
        h = g_a[idx] * h + g_b[idx];
        __nv_bfloat16 hh = __float2bfloat16(h);
        g_hhi[idx] = hh;
        g_hlo[idx] = __float2bfloat16(h - __bfloat162float(hh));
    }
}

// ---------------- launch ----------------
extern "C" void kernel_launch(void* const* d_in, const int* in_sizes, int n_in,
                              void* d_out, int out_size)
{
    const float* x    = (const float*)d_in[0];
    const float* Wa_w = (const float*)d_in[1];
    const float* Wa_b = (const float*)d_in[2];
    const float* B_w  = (const float*)d_in[3];
    const float* C_w  = (const float*)d_in[4];
    const float* D_w  = (const float*)d_in[5];
    float* y = (float*)d_out;

    cudaFuncSetAttribute(proj_kernel, cudaFuncAttributeMaxDynamicSharedMemorySize, SMEM_TOTAL);
    cudaFuncSetAttribute(out_kernel,  cudaFuncAttributeMaxDynamicSharedMemorySize, SMEM_TOTAL);

    // 1: fused operand split (all 5 tensors, one launch)
    split_all<<<F4_TOT / 256, 256>>>(x, Wa_w, B_w, C_w, D_w);

    // 2: projections
    dim3 blk(256);
    dim3 gproj(4, M_ROWS / 128);          // n-block fastest -> A reuse in L2
    proj_kernel<<<gproj, blk, SMEM_TOTAL>>>(Wa_b);

    // 3-5: scan
    scan_agg  <<<BATCH * NCHUNK, NS>>>(); // 1024 blocks
    scan_carry<<<BATCH, NS>>>();
    scan_apply<<<BATCH * NCHUNK, NS>>>(); // 1024 blocks

    // 6: output GEMM
    dim3 gout(DM / 128, M_ROWS / 128);    // n-block fastest -> A reuse in L2
    out_kernel<<<gout, blk, SMEM_TOTAL>>>(y);
}

// round 16
// speedup vs baseline: 1.1046x; 1.0029x over previous
#include <cuda_runtime.h>
#include <cuda_bf16.h>
#include <stdint.h>
#include <math.h>

// ---------------- problem constants ----------------
#define BATCH   8
#define SEQ     4096
#define DM      1024
#define NS      256
#define M_ROWS  (BATCH*SEQ)     // 32768
#define CHUNK   32
#define NCHUNK  (SEQ/CHUNK)     // 128

// ---------------- scratch ----------------
__device__ float g_a[M_ROWS * NS];
__device__ float g_b[M_ROWS * NS];
__device__ float g_Aagg[BATCH * NCHUNK * NS];
__device__ float g_Bagg[BATCH * NCHUNK * NS];
__device__ float g_carry[BATCH * NCHUNK * NS];

__device__ __nv_bfloat16 g_xhi[M_ROWS * DM], g_xlo[M_ROWS * DM];
__device__ __nv_bfloat16 g_hhi[M_ROWS * NS], g_hlo[M_ROWS * NS];
__device__ __nv_bfloat16 g_wahi[NS * DM],  g_walo[NS * DM];
__device__ __nv_bfloat16 g_bwhi[NS * DM],  g_bwlo[NS * DM];
__device__ __nv_bfloat16 g_chi[DM * NS],   g_clo[DM * NS];
__device__ __nv_bfloat16 g_dhi[DM * DM],   g_dlo[DM * DM];

// ---------------- GEMM config (128x128, 2 CTA/SM) ----------------
#define LDS_EL  40
#define A_SZ    (128 * LDS_EL * 2)      // 10240 B
#define STAGE   (4 * A_SZ)              // 40960 B
#define SMEM_TOTAL (2 * STAGE)          // 81920 B

// ---------------- PTX helpers ----------------
__device__ __forceinline__ uint32_t smem_u32(const void* p) {
    uint32_t a;
    asm("{ .reg .u64 t; cvta.to.shared.u64 t, %1; cvt.u32.u64 %0, t; }" : "=r"(a) : "l"(p));
    return a;
}
__device__ __forceinline__ void cp16(uint32_t d, const void* s) {
    asm volatile("cp.async.cg.shared.global [%0], [%1], 16;" :: "r"(d), "l"(s));
}
#define CP_COMMIT() asm volatile("cp.async.commit_group;" ::: "memory")
#define CP_WAIT(N)  asm volatile("cp.async.wait_group %0;" :: "n"(N) : "memory")

__device__ __forceinline__ void ldm4(uint32_t* r, uint32_t a) {
    asm volatile("ldmatrix.sync.aligned.m8n8.x4.shared.b16 {%0,%1,%2,%3}, [%4];"
        : "=r"(r[0]), "=r"(r[1]), "=r"(r[2]), "=r"(r[3]) : "r"(a));
}
__device__ __forceinline__ void mma16(float* c, const uint32_t* a, const uint32_t* b) {
    asm volatile("mma.sync.aligned.m16n8k16.row.col.f32.bf16.bf16.f32 "
        "{%0,%1,%2,%3}, {%4,%5,%6,%7}, {%8,%9}, {%0,%1,%2,%3};"
        : "+f"(c[0]), "+f"(c[1]), "+f"(c[2]), "+f"(c[3])
        : "r"(a[0]), "r"(a[1]), "r"(a[2]), "r"(a[3]), "r"(b[0]), "r"(b[1]));
}

// ---------------- per-slab compute: 3-pass bf16 compensation ----------------
__device__ __forceinline__ void compute_slab(uint32_t stg, float acc[4][4][4],
                                             int wr, int wc, int lane)
{
    const uint32_t aoff = ((wr * 64 + (lane & 15)) * LDS_EL + (lane >> 4) * 8) * 2;
    const uint32_t boff = ((wc * 32 + (lane & 15)) * LDS_EL + (lane >> 4) * 8) * 2;
    #pragma unroll
    for (int ks = 0; ks < 2; ks++) {
        const uint32_t kb = ks * 32;   // 16 bf16 = 32 B
        uint32_t ahi[4][4];
        #pragma unroll
        for (int i = 0; i < 4; i++) ldm4(ahi[i], stg + aoff + kb + i * (16 * LDS_EL * 2));

        uint32_t bh[4][2];
        {
            uint32_t t0[4], t1[4];
            ldm4(t0, stg + 2 * A_SZ + boff + kb);
            ldm4(t1, stg + 2 * A_SZ + boff + kb + 16 * LDS_EL * 2);
            bh[0][0] = t0[0]; bh[0][1] = t0[2]; bh[1][0] = t0[1]; bh[1][1] = t0[3];
            bh[2][0] = t1[0]; bh[2][1] = t1[2]; bh[3][0] = t1[1]; bh[3][1] = t1[3];
        }
        #pragma unroll
        for (int j = 0; j < 4; j++)
            #pragma unroll
            for (int i = 0; i < 4; i++) mma16(acc[i][j], ahi[i], bh[j]);   // hi*hi

        {
            uint32_t t0[4], t1[4], bl[4][2];
            ldm4(t0, stg + 3 * A_SZ + boff + kb);
            ldm4(t1, stg + 3 * A_SZ + boff + kb + 16 * LDS_EL * 2);
            bl[0][0] = t0[0]; bl[0][1] = t0[2]; bl[1][0] = t0[1]; bl[1][1] = t0[3];
            bl[2][0] = t1[0]; bl[2][1] = t1[2]; bl[3][0] = t1[1]; bl[3][1] = t1[3];
            #pragma unroll
            for (int j = 0; j < 4; j++)
                #pragma unroll
                for (int i = 0; i < 4; i++) mma16(acc[i][j], ahi[i], bl[j]); // hi*lo
        }
        {
            uint32_t alo[4][4];
            #pragma unroll
            for (int i = 0; i < 4; i++) ldm4(alo[i], stg + A_SZ + aoff + kb + i * (16 * LDS_EL * 2));
            #pragma unroll
            for (int j = 0; j < 4; j++)
                #pragma unroll
                for (int i = 0; i < 4; i++) mma16(acc[i][j], alo[i], bh[j]); // lo*hi
        }
    }
}

// ---------------- pipelined GEMM segment (single sync per slab) ----------------
__device__ __forceinline__ void gemm_pipe(
    const __nv_bfloat16* __restrict__ Ah, const __nv_bfloat16* __restrict__ Al, int lda, int m0,
    const __nv_bfloat16* __restrict__ Bh, const __nv_bfloat16* __restrict__ Bl, int ldb, int n0,
    int K, uint32_t sb, float acc[4][4][4])
{
    const int tid = threadIdx.x;
    const int warp = tid >> 5, lane = tid & 31;
    const int wr = warp >> 2, wc = warp & 3;

    const __nv_bfloat16* src0 = Ah + (size_t)m0 * lda;
    const __nv_bfloat16* src1 = Al + (size_t)m0 * lda;
    const __nv_bfloat16* src2 = Bh + (size_t)n0 * ldb;
    const __nv_bfloat16* src3 = Bl + (size_t)n0 * ldb;

    auto issue = [&](int slab, int buf) {
        const int k0 = slab * 32;
        const uint32_t db = sb + buf * STAGE;
        #pragma unroll
        for (int t = 0; t < 8; t++) {
            int id   = tid + t * 256;
            int tile = id >> 9;            // 512 16B-chunks per tile
            int c    = id & 511;
            int row  = c >> 2, seg = c & 3;
            const __nv_bfloat16* s;
            if      (tile == 0) s = src0 + (size_t)row * lda + k0 + seg * 8;
            else if (tile == 1) s = src1 + (size_t)row * lda + k0 + seg * 8;
            else if (tile == 2) s = src2 + (size_t)row * ldb + k0 + seg * 8;
            else                s = src3 + (size_t)row * ldb + k0 + seg * 8;
            cp16(db + tile * A_SZ + (row * LDS_EL + seg * 8) * 2, s);
        }
        CP_COMMIT();
    };

    const int nslab = K / 32;
    issue(0, 0);
    CP_WAIT(0);
    __syncthreads();
    for (int s = 0; s < nslab; s++) {
        if (s + 1 < nslab) issue(s + 1, (s + 1) & 1);   // overlaps compute(s)
        compute_slab(sb + (s & 1) * STAGE, acc, wr, wc, lane);
        if (s + 1 < nslab) {
            CP_WAIT(0);
            __syncthreads();
        }
    }
    __syncthreads();
}

// ---------------- fused split of all 5 f32 tensors -> bf16 hi/lo ----------------
#define F4_X   8388608u                    // M_ROWS*DM/4
#define F4_W   65536u                      // NS*DM/4 (== DM*NS/4)
#define F4_D   262144u                     // DM*DM/4
#define F4_TOT (F4_X + 3*F4_W + F4_D)      // 8847360 (divisible by 256)

__global__ void split_all(const float* __restrict__ x,  const float* __restrict__ wa,
                          const float* __restrict__ bw, const float* __restrict__ cw,
                          const float* __restrict__ dw)
{
    uint32_t id = blockIdx.x * blockDim.x + threadIdx.x;   // one float4
    const float* src; __nv_bfloat16 *hi, *lo; uint32_t off;
    if      (id < F4_X)          { src = x;  hi = g_xhi;  lo = g_xlo;  off = id; }
    else if (id < F4_X + F4_W)   { src = wa; hi = g_wahi; lo = g_walo; off = id - F4_X; }
    else if (id < F4_X + 2*F4_W) { src = bw; hi = g_bwhi; lo = g_bwlo; off = id - (F4_X + F4_W); }
    else if (id < F4_X + 3*F4_W) { src = cw; hi = g_chi;  lo = g_clo;  off = id - (F4_X + 2*F4_W); }
    else                         { src = dw; hi = g_dhi;  lo = g_dlo;  off = id - (F4_X + 3*F4_W); }

    size_t i = (size_t)off * 4;
    float4 v = *(const float4*)(src + i);
    __nv_bfloat16 h[4], l[4];
    h[0] = __float2bfloat16(v.x); l[0] = __float2bfloat16(v.x - __bfloat162float(h[0]));
    h[1] = __float2bfloat16(v.y); l[1] = __float2bfloat16(v.y - __bfloat162float(h[1]));
    h[2] = __float2bfloat16(v.z); l[2] = __float2bfloat16(v.z - __bfloat162float(h[2]));
    h[3] = __float2bfloat16(v.w); l[3] = __float2bfloat16(v.w - __bfloat162float(h[3]));
    *(uint2*)(hi + i) = *(uint2*)h;
    *(uint2*)(lo + i) = *(uint2*)l;
}

__global__ __launch_bounds__(256, 2)
void proj_kernel(const float* __restrict__ bias)
{
    extern __shared__ char smem[];
    uint32_t sb = smem_u32(smem);
    float acc[4][4][4] = {};

    const int m0 = blockIdx.y * 128;
    const int bx = blockIdx.x;               // 0,1 -> a; 2,3 -> b
    const bool is_a = (bx < 2);
    const int n0 = (bx & 1) * 128;
    const __nv_bfloat16* Wh = is_a ? g_wahi : g_bwhi;
    const __nv_bfloat16* Wl = is_a ? g_walo : g_bwlo;

    gemm_pipe(g_xhi, g_xlo, DM, m0, Wh, Wl, DM, n0, DM, sb, acc);

    float* dst = is_a ? g_a : g_b;
    const int warp = threadIdx.x >> 5, lane = threadIdx.x & 31;
    const int wr = warp >> 2, wc = warp & 3;
    const int gq = lane >> 2, tq = lane & 3;

    #pragma unroll
    for (int i = 0; i < 4; i++) {
        #pragma unroll
        for (int j = 0; j < 4; j++) {
            const int row = m0 + wr * 64 + i * 16 + gq;
            const int col = n0 + wc * 32 + j * 8 + tq * 2;
            float v0 = acc[i][j][0], v1 = acc[i][j][1];
            float v2 = acc[i][j][2], v3 = acc[i][j][3];
            if (is_a) {
                float b0 = bias[col], b1 = bias[col + 1];
                v0 = 1.0f / (1.0f + __expf(-(v0 + b0)));
                v1 = 1.0f / (1.0f + __expf(-(v1 + b1)));
                v2 = 1.0f / (1.0f + __expf(-(v2 + b0)));
                v3 = 1.0f / (1.0f + __expf(-(v3 + b1)));
            }
            *(float2*)&dst[(size_t)row * NS + col]       = make_float2(v0, v1);
            *(float2*)&dst[(size_t)(row + 8) * NS + col] = make_float2(v2, v3);
        }
    }
}

__global__ __launch_bounds__(256, 2)
void out_kernel(float* __restrict__ Y)
{
    extern __shared__ char smem[];
    uint32_t sb = smem_u32(smem);
    float acc[4][4][4] = {};

    const int m0 = blockIdx.y * 128;
    const int n0 = blockIdx.x * 128;

    gemm_pipe(g_hhi, g_hlo, NS, m0, g_chi, g_clo, NS, n0, NS, sb, acc); // h @ C^T
    gemm_pipe(g_xhi, g_xlo, DM, m0, g_dhi, g_dlo, DM, n0, DM, sb, acc); // x @ D^T

    const int warp = threadIdx.x >> 5, lane = threadIdx.x & 31;
    const int wr = warp >> 2, wc = warp & 3;
    const int gq = lane >> 2, tq = lane & 3;

    #pragma unroll
    for (int i = 0; i < 4; i++) {
        #pragma unroll
        for (int j = 0; j < 4; j++) {
            const int row = m0 + wr * 64 + i * 16 + gq;
            const int col = n0 + wc * 32 + j * 8 + tq * 2;
            *(float2*)&Y[(size_t)row * DM + col]       = make_float2(acc[i][j][0], acc[i][j][1]);
            *(float2*)&Y[(size_t)(row + 8) * DM + col] = make_float2(acc[i][j][2], acc[i][j][3]);
        }
    }
}

// ---------------- scan (CHUNK=32, 1024-block agg/apply) ----------------
__global__ void scan_agg()
{
    const int bc = blockIdx.x, n = threadIdx.x;
    const int b = bc / NCHUNK, c = bc % NCHUNK;
    size_t base = ((size_t)b * SEQ + (size_t)c * CHUNK) * NS + n;
    float A = 1.0f, Bv = 0.0f;
    #pragma unroll 8
    for (int s = 0; s < CHUNK; s++) {
        size_t idx = base + (size_t)s * NS;
        float a = g_a[idx], bb = g_b[idx];
        A = a * A; Bv = a * Bv + bb;
    }
    g_Aagg[(size_t)bc * NS + n] = A;
    g_Bagg[(size_t)bc * NS + n] = Bv;
}

// 128-step chain, group-of-16 prefetch (32 loads in flight)
__global__ void scan_carry()
{
    const int b = blockIdx.x, n = threadIdx.x;
    float h = 0.0f;
    for (int c = 0; c < NCHUNK; c += 16) {
        float A[16], Bv[16];
        #pragma unroll
        for (int j = 0; j < 16; j++) {
            size_t idx = ((size_t)b * NCHUNK + c + j) * NS + n;
            A[j]  = g_Aagg[idx];
            Bv[j] = g_Bagg[idx];
        }
        #pragma unroll
        for (int j = 0; j < 16; j++) {
            size_t idx = ((size_t)b * NCHUNK + c + j) * NS + n;
            g_carry[idx] = h;
            h = A[j] * h + Bv[j];
        }
    }
}

__global__ void scan_apply()
{
    const int bc = blockIdx.x, n = threadIdx.x;
    const int b = bc / NCHUNK, c = bc % NCHUNK;
    float h = g_carry[(size_t)bc * NS + n];
    size_t base = ((size_t)b * SEQ + (size_t)c * CHUNK) * NS + n;
    #pragma unroll 8
    for (int s = 0; s < CHUNK; s++) {
        size_t idx = base + (size_t)s * NS;
        h = g_a[idx] * h + g_b[idx];
        __nv_bfloat16 hh = __float2bfloat16(h);
        g_hhi[idx] = hh;
        g_hlo[idx] = __float2bfloat16(h - __bfloat162float(hh));
    }
}

// ---------------- launch ----------------
extern "C" void kernel_launch(void* const* d_in, const int* in_sizes, int n_in,
                              void* d_out, int out_size)
{
    const float* x    = (const float*)d_in[0];
    const float* Wa_w = (const float*)d_in[1];
    const float* Wa_b = (const float*)d_in[2];
    const float* B_w  = (const float*)d_in[3];
    const float* C_w  = (const float*)d_in[4];
    const float* D_w  = (const float*)d_in[5];
    float* y = (float*)d_out;

    cudaFuncSetAttribute(proj_kernel, cudaFuncAttributeMaxDynamicSharedMemorySize, SMEM_TOTAL);
    cudaFuncSetAttribute(out_kernel,  cudaFuncAttributeMaxDynamicSharedMemorySize, SMEM_TOTAL);

    // 1: fused operand split (all 5 tensors, one launch)
    split_all<<<F4_TOT / 256, 256>>>(x, Wa_w, B_w, C_w, D_w);

    // 2: projections
    dim3 blk(256);
    dim3 gproj(4, M_ROWS / 128);          // n-block fastest -> A reuse in L2
    proj_kernel<<<gproj, blk, SMEM_TOTAL>>>(Wa_b);

    // 3-5: scan
    scan_agg  <<<BATCH * NCHUNK, NS>>>(); // 1024 blocks
    scan_carry<<<BATCH, NS>>>();
    scan_apply<<<BATCH * NCHUNK, NS>>>(); // 1024 blocks

    // 6: output GEMM
    dim3 gout(DM / 128, M_ROWS / 128);    // n-block fastest -> A reuse in L2
    out_kernel<<<gout, blk, SMEM_TOTAL>>>(y);
}